// round 1
// baseline (speedup 1.0000x reference)
#include <cuda_runtime.h>
#include <cuda_bf16.h>

#define FFT_N 4096
#define TPB   512   // = FFT_N / 8

// Padded shared index: +1 float2 per 16 -> conflict-free stride-512 reads and
// conflict-free radix-8 scatter writes at stage 0.
__device__ __forceinline__ int spad(int i) { return i + (i >> 4); }

__device__ __forceinline__ float2 cadd(float2 a, float2 b) { return make_float2(a.x + b.x, a.y + b.y); }
__device__ __forceinline__ float2 csub(float2 a, float2 b) { return make_float2(a.x - b.x, a.y - b.y); }
// multiply by -i : (x + iy)(-i) = y - ix
__device__ __forceinline__ float2 cmul_mi(float2 a) { return make_float2(a.y, -a.x); }

// In-place natural-order 8-point DFT: a[m] <- sum_j a[j] * W8^(j*m), W8 = e^{-i pi/4}
__device__ __forceinline__ void dft8(float2* a)
{
    const float C = 0.70710678118654752440f;
    float2 t;

    float2 u0 = cadd(a[0], a[4]);
    float2 v0 = csub(a[0], a[4]);
    float2 u1 = cadd(a[1], a[5]);
    t         = csub(a[1], a[5]);                       // * W8^1 = c - ic
    float2 v1 = make_float2(C * (t.x + t.y), C * (t.y - t.x));
    float2 u2 = cadd(a[2], a[6]);
    t         = csub(a[2], a[6]);                       // * W8^2 = -i
    float2 v2 = make_float2(t.y, -t.x);
    float2 u3 = cadd(a[3], a[7]);
    t         = csub(a[3], a[7]);                       // * W8^3 = -c - ic
    float2 v3 = make_float2(C * (t.y - t.x), -C * (t.x + t.y));

    // DFT4(u) -> outputs 0,2,4,6
    float2 p0 = cadd(u0, u2), q0 = csub(u0, u2);
    float2 p1 = cadd(u1, u3);
    float2 q1 = cmul_mi(csub(u1, u3));
    a[0] = cadd(p0, p1);  a[4] = csub(p0, p1);
    a[2] = cadd(q0, q1);  a[6] = csub(q0, q1);

    // DFT4(v) -> outputs 1,3,5,7
    p0 = cadd(v0, v2);  q0 = csub(v0, v2);
    p1 = cadd(v1, v3);
    q1 = cmul_mi(csub(v1, v3));
    a[1] = cadd(p0, p1);  a[5] = csub(p0, p1);
    a[3] = cadd(q0, q1);  a[7] = csub(q0, q1);
}

// Stockham twiddle: a[r] *= exp(-2*pi*i * r * (j mod Ns) / (8*Ns)), r = 0..7.
// One __sincosf (|ang| < pi/4 -> high accuracy region), then chain w^r with FMAs.
template <int Ns>
__device__ __forceinline__ void twiddle(float2* a, int j)
{
    const int   p   = j & (Ns - 1);
    const float k   = -6.2831853071795864769f / (8.0f * (float)Ns);
    float s, c;
    __sincosf(k * (float)p, &s, &c);
    float wx = c, wy = s;      // w
    float cx = c, cy = s;      // w^r running product
#pragma unroll
    for (int r = 1; r < 8; ++r) {
        float xr = a[r].x, xi = a[r].y;
        a[r].x = xr * cx - xi * cy;
        a[r].y = xr * cy + xi * cx;
        float nx = cx * wx - cy * wy;
        float ny = cx * wy + cy * wx;
        cx = nx; cy = ny;
    }
}

__global__ void __launch_bounds__(TPB)
fft4096_kernel(const float* __restrict__ xre, const float* __restrict__ xim,
               float* __restrict__ yre, float* __restrict__ yim)
{
    __shared__ float2 buf[FFT_N + (FFT_N >> 4)];   // 34.0 KB padded

    const int    j    = threadIdx.x;               // 0..511
    const size_t base = (size_t)blockIdx.x * FFT_N;

    float2 a[8];

    // ---- stage 0 (Ns = 1): load coalesced from global, no twiddle ----
#pragma unroll
    for (int r = 0; r < 8; ++r) {
        int idx = j + (r << 9);
        a[r].x = xre[base + idx];
        a[r].y = xim[base + idx];
    }
    dft8(a);
#pragma unroll
    for (int m = 0; m < 8; ++m)
        buf[spad((j << 3) + m)] = a[m];            // idxD = 8j, +m*1
    __syncthreads();

    // ---- stage 1 (Ns = 8) ----
#pragma unroll
    for (int r = 0; r < 8; ++r)
        a[r] = buf[spad(j + (r << 9))];
    __syncthreads();                                // in-place: all reads before writes
    twiddle<8>(a, j);
    dft8(a);
    {
        const int idxD = ((j >> 3) << 6) | (j & 7);
#pragma unroll
        for (int m = 0; m < 8; ++m)
            buf[spad(idxD + (m << 3))] = a[m];
    }
    __syncthreads();

    // ---- stage 2 (Ns = 64) ----
#pragma unroll
    for (int r = 0; r < 8; ++r)
        a[r] = buf[spad(j + (r << 9))];
    __syncthreads();
    twiddle<64>(a, j);
    dft8(a);
    {
        const int idxD = ((j >> 6) << 9) | (j & 63);
#pragma unroll
        for (int m = 0; m < 8; ++m)
            buf[spad(idxD + (m << 6))] = a[m];
    }
    __syncthreads();

    // ---- stage 3 (Ns = 512): idxD = j, write coalesced straight to global ----
#pragma unroll
    for (int r = 0; r < 8; ++r)
        a[r] = buf[spad(j + (r << 9))];
    twiddle<512>(a, j);
    dft8(a);
#pragma unroll
    for (int m = 0; m < 8; ++m) {
        const int idx = j + (m << 9);
        yre[base + idx] = a[m].x;
        yim[base + idx] = a[m].y;
    }
}

extern "C" void kernel_launch(void* const* d_in, const int* in_sizes, int n_in,
                              void* d_out, int out_size)
{
    const float* xre = (const float*)d_in[0];
    const float* xim = (const float*)d_in[1];
    float*       out = (float*)d_out;

    const int rows = in_sizes[0] / FFT_N;          // 4096
    float* yre = out;
    float* yim = out + (size_t)rows * FFT_N;       // output tuple: [y_re | y_im]

    fft4096_kernel<<<rows, TPB>>>(xre, xim, yre, yim);
}

// round 2
// speedup vs baseline: 1.1139x; 1.1139x over previous
#include <cuda_runtime.h>
#include <cuda_bf16.h>

#define FFT_N 4096
#define TPB   256   // = FFT_N / 16, radix-16, 3 stages

// XOR swizzle: conflict-free for every access pattern in this kernel
// (stride-256 reads, 16-contig scatter writes, stride-16 writes), no padding.
__device__ __forceinline__ int sw(int i) { return i ^ ((i >> 4) & 15); }

__device__ __forceinline__ float2 cadd(float2 a, float2 b) { return make_float2(a.x + b.x, a.y + b.y); }
__device__ __forceinline__ float2 csub(float2 a, float2 b) { return make_float2(a.x - b.x, a.y - b.y); }
// multiply by -i : (x + iy)(-i) = y - ix
__device__ __forceinline__ float2 cmul_mi(float2 a) { return make_float2(a.y, -a.x); }
__device__ __forceinline__ float2 cmul(float2 a, float2 b)
{ return make_float2(a.x * b.x - a.y * b.y, a.x * b.y + a.y * b.x); }

// In-place natural-order DFT4: x[k] <- sum_n x[n] W4^{nk}, W4 = -i
__device__ __forceinline__ void dft4(float2& x0, float2& x1, float2& x2, float2& x3)
{
    float2 t0 = cadd(x0, x2);
    float2 t1 = csub(x0, x2);
    float2 t2 = cadd(x1, x3);
    float2 t3 = cmul_mi(csub(x1, x3));
    x0 = cadd(t0, t2);
    x1 = cadd(t1, t3);
    x2 = csub(t0, t2);
    x3 = csub(t1, t3);
}

// DFT16 on natural-order input a[0..15]. On exit, slot a[k1 + 4*k2] holds
// output bin X[k2 + 4*k1] (digit-swapped); callers apply perm(i) at the store.
__device__ __forceinline__ void dft16(float2* a)
{
    // inner DFT4 over n2 (stride 4), one per n1; result y[n1][k2] at a[n1 + 4*k2]
    dft4(a[0], a[4], a[8],  a[12]);
    dft4(a[1], a[5], a[9],  a[13]);
    dft4(a[2], a[6], a[10], a[14]);
    dft4(a[3], a[7], a[11], a[15]);

    const float c8 = 0.92387953251128675613f;   // cos(pi/8)
    const float s8 = 0.38268343236508977173f;   // sin(pi/8)
    const float r2 = 0.70710678118654752440f;   // cos(pi/4)

    // twiddle y[n1][k2] *= W16^{n1*k2}
    a[5]  = cmul(a[5],  make_float2( c8, -s8));  // W^1
    a[6]  = cmul(a[6],  make_float2( r2, -r2));  // W^2
    a[7]  = cmul(a[7],  make_float2( s8, -c8));  // W^3
    a[9]  = cmul(a[9],  make_float2( r2, -r2));  // W^2
    a[10] = cmul_mi(a[10]);                      // W^4 = -i
    a[11] = cmul(a[11], make_float2(-r2, -r2));  // W^6
    a[13] = cmul(a[13], make_float2( s8, -c8));  // W^3
    a[14] = cmul(a[14], make_float2(-r2, -r2));  // W^6
    a[15] = cmul(a[15], make_float2(-c8,  s8));  // W^9

    // outer DFT4 over n1 for each k2: slot n1+4k2 -> X[k2 + 4*n1]
    dft4(a[0],  a[1],  a[2],  a[3]);
    dft4(a[4],  a[5],  a[6],  a[7]);
    dft4(a[8],  a[9],  a[10], a[11]);
    dft4(a[12], a[13], a[14], a[15]);
}

// output-bin index held in slot i after dft16
__device__ __forceinline__ int perm16(int i) { return (i >> 2) | ((i & 3) << 2); }

// Stockham inter-stage twiddle: a[r] *= exp(-2*pi*i * r * (j mod Ns) / (16*Ns))
template <int Ns>
__device__ __forceinline__ void twiddle16(float2* a, int j)
{
    const int   p = j & (Ns - 1);
    const float k = -6.2831853071795864769f / (16.0f * (float)Ns);
    float s, c;
    __sincosf(k * (float)p, &s, &c);          // |angle| < 2*pi/16 -> accurate
    float wx = c, wy = s;                     // w
    float cx = c, cy = s;                     // running w^r
#pragma unroll
    for (int r = 1; r < 16; ++r) {
        float xr = a[r].x, xi = a[r].y;
        a[r].x = xr * cx - xi * cy;
        a[r].y = xr * cy + xi * cx;
        float nx = cx * wx - cy * wy;
        float ny = cx * wy + cy * wx;
        cx = nx; cy = ny;
    }
}

__global__ void __launch_bounds__(TPB, 2)
fft4096_r16(const float* __restrict__ xre, const float* __restrict__ xim,
            float* __restrict__ yre, float* __restrict__ yim)
{
    __shared__ float2 buf[FFT_N];              // 32 KB, XOR-swizzled

    const int    j    = threadIdx.x;           // 0..255
    const size_t base = (size_t)blockIdx.x * FFT_N;

    float2 a[16];

    // ---- stage 0 (Ns = 1): coalesced global load, no inter-stage twiddle ----
#pragma unroll
    for (int r = 0; r < 16; ++r) {
        const int idx = j + (r << 8);
        a[r].x = xre[base + idx];
        a[r].y = xim[base + idx];
    }
    dft16(a);
#pragma unroll
    for (int i = 0; i < 16; ++i)
        buf[sw((j << 4) + perm16(i))] = a[i];  // idxD = 16j, +m
    __syncthreads();

    // ---- stage 1 (Ns = 16) ----
#pragma unroll
    for (int r = 0; r < 16; ++r)
        a[r] = buf[sw(j + (r << 8))];
    __syncthreads();                           // in-place: reads before writes
    twiddle16<16>(a, j);
    dft16(a);
    {
        const int idxD = ((j >> 4) << 8) | (j & 15);
#pragma unroll
        for (int i = 0; i < 16; ++i)
            buf[sw(idxD + (perm16(i) << 4))] = a[i];
    }
    __syncthreads();

    // ---- stage 2 (Ns = 256): idxD = j, coalesced global store ----
#pragma unroll
    for (int r = 0; r < 16; ++r)
        a[r] = buf[sw(j + (r << 8))];
    twiddle16<256>(a, j);
    dft16(a);
#pragma unroll
    for (int i = 0; i < 16; ++i) {
        const int idx = j + (perm16(i) << 8);
        yre[base + idx] = a[i].x;
        yim[base + idx] = a[i].y;
    }
}

extern "C" void kernel_launch(void* const* d_in, const int* in_sizes, int n_in,
                              void* d_out, int out_size)
{
    const float* xre = (const float*)d_in[0];
    const float* xim = (const float*)d_in[1];
    float*       out = (float*)d_out;

    const int rows = in_sizes[0] / FFT_N;      // 4096
    float* yre = out;
    float* yim = out + (size_t)rows * FFT_N;   // output tuple: [y_re | y_im]

    fft4096_r16<<<rows, TPB>>>(xre, xim, yre, yim);
}